// round 14
// baseline (speedup 1.0000x reference)
#include <cuda_runtime.h>

#define B 128
#define K 17
#define HW 9216          // 96*96
#define NVEC (HW/4)      // 2304
#define TOPK 8
#define THREADS1 256
#define NPJ (B * K)      // 2176
#define T2 1024

__device__ float g_per_joint[B * K];

__global__ void __launch_bounds__(THREADS1, 4)
mse_per_joint_kernel(const float* __restrict__ pred,
                     const float* __restrict__ gt,
                     const float* __restrict__ tw) {
#if __CUDA_ARCH__ >= 900
    // Fire PDL trigger immediately: lets the dependent topk kernel start its
    // launch prologue while we stream. Its cudaGridDependencySynchronize()
    // still waits for ALL our writes, so this is safe at kernel entry.
    cudaTriggerProgrammaticLaunchCompletion();
#endif
    const int bk = blockIdx.x;                    // 0 .. B*K-1
    const float4* __restrict__ p = reinterpret_cast<const float4*>(pred + (size_t)bk * HW);
    const float4* __restrict__ g = reinterpret_cast<const float4*>(gt   + (size_t)bk * HW);

    float acc = 0.0f;
    #pragma unroll
    for (int j = 0; j < NVEC / THREADS1; j++) {   // 9 iterations, fully unrolled
        const int i = threadIdx.x + j * THREADS1;
        float4 a = p[i];
        float4 b = g[i];
        float d0 = a.x - b.x;
        float d1 = a.y - b.y;
        float d2 = a.z - b.z;
        float d3 = a.w - b.w;
        acc += d0 * d0 + d1 * d1 + d2 * d2 + d3 * d3;
    }

    // warp reduce
    #pragma unroll
    for (int off = 16; off > 0; off >>= 1)
        acc += __shfl_down_sync(0xFFFFFFFFu, acc, off);

    __shared__ float warp_sums[THREADS1 / 32];
    const int lane = threadIdx.x & 31;
    const int wid  = threadIdx.x >> 5;
    if (lane == 0) warp_sums[wid] = acc;
    __syncthreads();

    if (wid == 0) {
        float v = (lane < THREADS1 / 32) ? warp_sums[lane] : 0.0f;
        #pragma unroll
        for (int off = 4; off > 0; off >>= 1)
            v += __shfl_down_sync(0xFFFFFFFFu, v, off);
        if (lane == 0) {
            const float w = tw[bk];
            g_per_joint[bk] = v * w * w * (1.0f / (float)HW);
        }
    }
}

__global__ void __launch_bounds__(T2, 1)
ohkm_topk_kernel(float* __restrict__ out) {
#if __CUDA_ARCH__ >= 900
    // Launched via PDL: we are on-chip while the primary streams.
    // This waits (HW sleep, no L2 polling) until all primary writes land.
    cudaGridDependencySynchronize();
#endif
    const int tid  = threadIdx.x;
    const int lane = tid & 31;
    const int wid  = tid >> 5;

    __shared__ float pj[NPJ];        // all per-joint values, loaded in parallel
    __shared__ float wsum[4];

    // ---- phase 1: gang-load 2176 floats (fully parallel, one L2 trip) ----
    {
        float v0 = g_per_joint[tid];
        float v1 = g_per_joint[tid + T2];
        float v2 = (tid < NPJ - 2 * T2) ? g_per_joint[tid + 2 * T2] : 0.0f;
        pj[tid] = v0;
        pj[tid + T2] = v1;
        if (tid < NPJ - 2 * T2) pj[tid + 2 * T2] = v2;
    }
    __syncthreads();

    // ---- phase 2: threads 0..127 do top-8 from hot smem ----
    float s = 0.0f;
    if (tid < B) {
        float t[TOPK];
        #pragma unroll
        for (int j = 0; j < TOPK; j++) t[j] = -3.4e38f;

        #pragma unroll
        for (int i = 0; i < K; i++) {
            float x = pj[tid * K + i];
            #pragma unroll
            for (int j = 0; j < TOPK; j++) {
                float o = t[j];
                bool gtp = x > o;
                t[j] = gtp ? x : o;
                x    = gtp ? o : x;
            }
        }
        #pragma unroll
        for (int j = 0; j < TOPK; j++) s += t[j];
    }

    // ---- phase 3: shuffle reduce (warps 0..3 hold the 128 sums) ----
    if (wid < 4) {
        #pragma unroll
        for (int off = 16; off > 0; off >>= 1)
            s += __shfl_down_sync(0xFFFFFFFFu, s, off);
        if (lane == 0) wsum[wid] = s;
    }
    __syncthreads();
    if (tid == 0)
        out[0] = (wsum[0] + wsum[1] + wsum[2] + wsum[3])
                 * (1.0f / (float)(B * TOPK));
}

extern "C" void kernel_launch(void* const* d_in, const int* in_sizes, int n_in,
                              void* d_out, int out_size) {
    const float* pred = (const float*)d_in[0];   // output [B,K,H,W]
    const float* gt   = (const float*)d_in[1];   // target [B,K,H,W]
    const float* tw   = (const float*)d_in[2];   // target_weight [B,K,1]
    float* out = (float*)d_out;

    mse_per_joint_kernel<<<NPJ, THREADS1>>>(pred, gt, tw);

    // Secondary with Programmatic Dependent Launch: overlaps its launch
    // prologue with the primary's streaming phase.
    cudaLaunchConfig_t cfg = {};
    cfg.gridDim = dim3(1, 1, 1);
    cfg.blockDim = dim3(T2, 1, 1);
    cfg.dynamicSmemBytes = 0;
    cfg.stream = 0;
    cudaLaunchAttribute attr[1];
    attr[0].id = cudaLaunchAttributeProgrammaticStreamSerialization;
    attr[0].val.programmaticStreamSerializationAllowed = 1;
    cfg.attrs = attr;
    cfg.numAttrs = 1;
    cudaError_t e = cudaLaunchKernelEx(&cfg, ohkm_topk_kernel, out);
    if (e != cudaSuccess) {
        // Fallback: plain serialized launch (correct, just not overlapped)
        ohkm_topk_kernel<<<1, T2>>>(out);
    }
}

// round 15
// speedup vs baseline: 1.0240x; 1.0240x over previous
#include <cuda_runtime.h>

#define B 128
#define K 17
#define HW 9216          // 96*96
#define NVEC (HW/4)      // 2304
#define TOPK 8
#define THREADS1 256
#define NPJ (B * K)      // 2176
#define T2 1024

__device__ float g_per_joint[B * K];

__global__ void __launch_bounds__(THREADS1, 4)
mse_per_joint_kernel(const float* __restrict__ pred,
                     const float* __restrict__ gt,
                     const float* __restrict__ tw) {
    const int bk = blockIdx.x;                    // 0 .. B*K-1
    const float4* __restrict__ p = reinterpret_cast<const float4*>(pred + (size_t)bk * HW);
    const float4* __restrict__ g = reinterpret_cast<const float4*>(gt   + (size_t)bk * HW);

    float acc = 0.0f;
    #pragma unroll
    for (int j = 0; j < NVEC / THREADS1; j++) {   // 9 iterations, fully unrolled
        const int i = threadIdx.x + j * THREADS1;
        // evict-first streaming loads: read-once data, don't pollute L2/L1
        float4 a = __ldcs(&p[i]);
        float4 b = __ldcs(&g[i]);
        float d0 = a.x - b.x;
        float d1 = a.y - b.y;
        float d2 = a.z - b.z;
        float d3 = a.w - b.w;
        acc += d0 * d0 + d1 * d1 + d2 * d2 + d3 * d3;
    }

    // warp reduce
    #pragma unroll
    for (int off = 16; off > 0; off >>= 1)
        acc += __shfl_down_sync(0xFFFFFFFFu, acc, off);

    __shared__ float warp_sums[THREADS1 / 32];
    const int lane = threadIdx.x & 31;
    const int wid  = threadIdx.x >> 5;
    if (lane == 0) warp_sums[wid] = acc;
    __syncthreads();

    if (wid == 0) {
        float v = (lane < THREADS1 / 32) ? warp_sums[lane] : 0.0f;
        #pragma unroll
        for (int off = 4; off > 0; off >>= 1)
            v += __shfl_down_sync(0xFFFFFFFFu, v, off);
        if (lane == 0) {
            const float w = tw[bk];
            g_per_joint[bk] = v * w * w * (1.0f / (float)HW);
        }
    }
}

__global__ void __launch_bounds__(T2, 1)
ohkm_topk_kernel(float* __restrict__ out) {
    const int tid  = threadIdx.x;
    const int lane = tid & 31;
    const int wid  = tid >> 5;

    __shared__ float pj[NPJ];        // all per-joint values, loaded in parallel
    __shared__ float wsum[4];

    // ---- phase 1: gang-load 2176 floats (fully parallel, one L2 trip) ----
    {
        float v0 = g_per_joint[tid];
        float v1 = g_per_joint[tid + T2];
        float v2 = (tid < NPJ - 2 * T2) ? g_per_joint[tid + 2 * T2] : 0.0f;
        pj[tid] = v0;
        pj[tid + T2] = v1;
        if (tid < NPJ - 2 * T2) pj[tid + 2 * T2] = v2;
    }
    __syncthreads();

    // ---- phase 2: threads 0..127 do top-8 from hot smem ----
    float s = 0.0f;
    if (tid < B) {
        float t[TOPK];
        #pragma unroll
        for (int j = 0; j < TOPK; j++) t[j] = -3.4e38f;

        #pragma unroll
        for (int i = 0; i < K; i++) {
            float x = pj[tid * K + i];
            #pragma unroll
            for (int j = 0; j < TOPK; j++) {
                float o = t[j];
                bool gtp = x > o;
                t[j] = gtp ? x : o;
                x    = gtp ? o : x;
            }
        }
        #pragma unroll
        for (int j = 0; j < TOPK; j++) s += t[j];
    }

    // ---- phase 3: shuffle reduce (warps 0..3 hold the 128 sums) ----
    if (wid < 4) {
        #pragma unroll
        for (int off = 16; off > 0; off >>= 1)
            s += __shfl_down_sync(0xFFFFFFFFu, s, off);
        if (lane == 0) wsum[wid] = s;
    }
    __syncthreads();
    if (tid == 0)
        out[0] = (wsum[0] + wsum[1] + wsum[2] + wsum[3])
                 * (1.0f / (float)(B * TOPK));
}

extern "C" void kernel_launch(void* const* d_in, const int* in_sizes, int n_in,
                              void* d_out, int out_size) {
    const float* pred = (const float*)d_in[0];   // output [B,K,H,W]
    const float* gt   = (const float*)d_in[1];   // target [B,K,H,W]
    const float* tw   = (const float*)d_in[2];   // target_weight [B,K,1]
    float* out = (float*)d_out;

    mse_per_joint_kernel<<<NPJ, THREADS1>>>(pred, gt, tw);
    ohkm_topk_kernel<<<1, T2>>>(out);
}

// round 16
// speedup vs baseline: 1.0779x; 1.0526x over previous
#include <cuda_runtime.h>

#define B 128
#define K 17
#define HW 9216          // 96*96
#define NVEC (HW/4)      // 2304
#define TOPK 8
#define THREADS1 256
#define NPJ (B * K)      // 2176
#define JPB 2            // joints per block
#define NBLK (NPJ / JPB) // 1088
#define T2 1024

__device__ float g_per_joint[B * K];

__global__ void __launch_bounds__(THREADS1, 4)
mse_per_joint_kernel(const float* __restrict__ pred,
                     const float* __restrict__ gt,
                     const float* __restrict__ tw) {
    const int bk0 = blockIdx.x * JPB;             // first joint of this block
    const int tid = threadIdx.x;
    const float4* __restrict__ p0 = reinterpret_cast<const float4*>(pred + (size_t)bk0 * HW);
    const float4* __restrict__ g0 = reinterpret_cast<const float4*>(gt   + (size_t)bk0 * HW);
    const float4* __restrict__ p1 = p0 + NVEC;
    const float4* __restrict__ g1 = g0 + NVEC;

    float acc0 = 0.0f, acc1 = 0.0f;
    #pragma unroll
    for (int j = 0; j < NVEC / THREADS1; j++) {   // 9 iters, 4 indep loads each
        const int i = tid + j * THREADS1;
        float4 a0 = p0[i];
        float4 b0 = g0[i];
        float4 a1 = p1[i];
        float4 b1 = g1[i];
        float d0 = a0.x - b0.x, d1 = a0.y - b0.y,
              d2 = a0.z - b0.z, d3 = a0.w - b0.w;
        acc0 += d0 * d0 + d1 * d1 + d2 * d2 + d3 * d3;
        d0 = a1.x - b1.x; d1 = a1.y - b1.y;
        d2 = a1.z - b1.z; d3 = a1.w - b1.w;
        acc1 += d0 * d0 + d1 * d1 + d2 * d2 + d3 * d3;
    }

    // warp reduce both accumulators
    #pragma unroll
    for (int off = 16; off > 0; off >>= 1) {
        acc0 += __shfl_down_sync(0xFFFFFFFFu, acc0, off);
        acc1 += __shfl_down_sync(0xFFFFFFFFu, acc1, off);
    }

    __shared__ float warp_sums[JPB][THREADS1 / 32];
    const int lane = tid & 31;
    const int wid  = tid >> 5;
    if (lane == 0) {
        warp_sums[0][wid] = acc0;
        warp_sums[1][wid] = acc1;
    }
    __syncthreads();

    // warp 0 folds joint 0, warp 1 folds joint 1
    if (wid < JPB) {
        float v = (lane < THREADS1 / 32) ? warp_sums[wid][lane] : 0.0f;
        #pragma unroll
        for (int off = 4; off > 0; off >>= 1)
            v += __shfl_down_sync(0xFFFFFFFFu, v, off);
        if (lane == 0) {
            const int bk = bk0 + wid;
            const float w = tw[bk];
            g_per_joint[bk] = v * w * w * (1.0f / (float)HW);
        }
    }
}

__global__ void __launch_bounds__(T2, 1)
ohkm_topk_kernel(float* __restrict__ out) {
    const int tid  = threadIdx.x;
    const int lane = tid & 31;
    const int wid  = tid >> 5;

    __shared__ float pj[NPJ];        // all per-joint values, loaded in parallel
    __shared__ float wsum[4];

    // ---- phase 1: gang-load 2176 floats (fully parallel, one L2 trip) ----
    {
        float v0 = g_per_joint[tid];
        float v1 = g_per_joint[tid + T2];
        float v2 = (tid < NPJ - 2 * T2) ? g_per_joint[tid + 2 * T2] : 0.0f;
        pj[tid] = v0;
        pj[tid + T2] = v1;
        if (tid < NPJ - 2 * T2) pj[tid + 2 * T2] = v2;
    }
    __syncthreads();

    // ---- phase 2: threads 0..127 do top-8 from hot smem ----
    float s = 0.0f;
    if (tid < B) {
        float t[TOPK];
        #pragma unroll
        for (int j = 0; j < TOPK; j++) t[j] = -3.4e38f;

        #pragma unroll
        for (int i = 0; i < K; i++) {
            float x = pj[tid * K + i];
            #pragma unroll
            for (int j = 0; j < TOPK; j++) {
                float o = t[j];
                bool gtp = x > o;
                t[j] = gtp ? x : o;
                x    = gtp ? o : x;
            }
        }
        #pragma unroll
        for (int j = 0; j < TOPK; j++) s += t[j];
    }

    // ---- phase 3: shuffle reduce (warps 0..3 hold the 128 sums) ----
    if (wid < 4) {
        #pragma unroll
        for (int off = 16; off > 0; off >>= 1)
            s += __shfl_down_sync(0xFFFFFFFFu, s, off);
        if (lane == 0) wsum[wid] = s;
    }
    __syncthreads();
    if (tid == 0)
        out[0] = (wsum[0] + wsum[1] + wsum[2] + wsum[3])
                 * (1.0f / (float)(B * TOPK));
}

extern "C" void kernel_launch(void* const* d_in, const int* in_sizes, int n_in,
                              void* d_out, int out_size) {
    const float* pred = (const float*)d_in[0];   // output [B,K,H,W]
    const float* gt   = (const float*)d_in[1];   // target [B,K,H,W]
    const float* tw   = (const float*)d_in[2];   // target_weight [B,K,1]
    float* out = (float*)d_out;

    mse_per_joint_kernel<<<NBLK, THREADS1>>>(pred, gt, tw);
    ohkm_topk_kernel<<<1, T2>>>(out);
}